// round 4
// baseline (speedup 1.0000x reference)
#include <cuda_runtime.h>

__device__ __forceinline__ float patch_ev(float t0, float t1, float t2, float t3,
                                          float4 A, float4 B, float4 Wv) {
    float s, c;
    __sincosf(t0, &s, &c); float d0 = fmaf(A.x, c, B.x * s);
    __sincosf(t1, &s, &c); float d1 = fmaf(A.y, c, B.y * s);
    __sincosf(t2, &s, &c); float d2 = fmaf(A.z, c, B.z * s);
    __sincosf(t3, &s, &c); float d3 = fmaf(A.w, c, B.w * s);
    // W0*d0 + W1*d0*d1 + W2*d0*d1*d2 + W3*d0*d1*d2*d3 (Horner)
    return d0 * fmaf(d1, fmaf(d2, fmaf(d3, Wv.w, Wv.z), Wv.y), Wv.x);
}

// One thread computes 8 patches: column-pair jj at patch-rows {i, i+7} for
// images {b, b+4096}. Threads: 4096 * 7 * 7 = 200704 = 1568 * 128 (exact).
__global__ void __launch_bounds__(128)
quanv_kernel(const float* __restrict__ x, const float* __restrict__ params,
             const float* __restrict__ W, float* __restrict__ out) {
    __shared__ __align__(16) float sqc[12];   // A0..3, B0..3, W0..3

    if (threadIdx.x < 4) {
        int w = threadIdx.x;
        float a = params[3 * w + 0];
        float b = params[3 * w + 1];
        // params[3w+2] (Rz) is diagonal-phase: no effect on Z expvals.
        sqc[w]     = cosf(a) * cosf(b);   // A_w
        sqc[4 + w] = -sinf(b);            // B_w
        sqc[8 + w] = W[w];
    }
    __syncthreads();

    int t  = blockIdx.x * 128 + threadIdx.x;
    int jj = t % 7;           // pair-of-patches column (j = 2jj, 2jj+1)
    int r  = t / 7;
    int i  = r % 7;           // patch row in [0,7); also handles i+7
    int b  = r / 7;           // image in [0,4096); also handles b+4096

    const int IMG4 = 4096 * 196;   // float4 stride to image b+4096
    const int IMG2 = 4096 * 98;    // float2 stride in output

    // x (B,1,28,28) f32: float4 row-chunk index = b*196 + i*14 + jj
    const float4* xr = reinterpret_cast<const float4*>(x);
    int o0 = b * 196 + i * 14 + jj;
    // 8 independent front-batched loads (MLP=8), all 128B-coalesced across the warp
    float4 r0 = xr[o0];                // image b,      row 2i
    float4 r1 = xr[o0 + 7];            // image b,      row 2i+1
    float4 r2 = xr[o0 + 98];           // image b,      row 2(i+7)
    float4 r3 = xr[o0 + 105];          // image b,      row 2(i+7)+1
    float4 s0 = xr[o0 + IMG4];         // image b+4096, row 2i
    float4 s1 = xr[o0 + IMG4 + 7];
    float4 s2 = xr[o0 + IMG4 + 98];
    float4 s3 = xr[o0 + IMG4 + 105];

    const float4* qc = reinterpret_cast<const float4*>(sqc);
    float4 Av = qc[0], Bv = qc[1], Wv = qc[2];

    float2 oA, oB, oC, oD;
    oA.x = patch_ev(r0.x, r0.y, r1.x, r1.y, Av, Bv, Wv);
    oA.y = patch_ev(r0.z, r0.w, r1.z, r1.w, Av, Bv, Wv);
    oB.x = patch_ev(r2.x, r2.y, r3.x, r3.y, Av, Bv, Wv);
    oB.y = patch_ev(r2.z, r2.w, r3.z, r3.w, Av, Bv, Wv);
    oC.x = patch_ev(s0.x, s0.y, s1.x, s1.y, Av, Bv, Wv);
    oC.y = patch_ev(s0.z, s0.w, s1.z, s1.w, Av, Bv, Wv);
    oD.x = patch_ev(s2.x, s2.y, s3.x, s3.y, Av, Bv, Wv);
    oD.y = patch_ev(s2.z, s2.w, s3.z, s3.w, Av, Bv, Wv);

    // out (B,196): float2 index b*98 + i*7 + jj; +49 for row i+7; +IMG2 for image b+4096
    float2* o2 = reinterpret_cast<float2*>(out);
    int q0 = b * 98 + i * 7 + jj;
    o2[q0]             = oA;
    o2[q0 + 49]        = oB;
    o2[q0 + IMG2]      = oC;
    o2[q0 + IMG2 + 49] = oD;
}

extern "C" void kernel_launch(void* const* d_in, const int* in_sizes, int n_in,
                              void* d_out, int out_size) {
    const float* x      = (const float*)d_in[0];
    const float* params = (const float*)d_in[1];
    const float* W      = (const float*)d_in[2];
    float* out          = (float*)d_out;

    quanv_kernel<<<1568, 128>>>(x, params, W, out);
}